// round 3
// baseline (speedup 1.0000x reference)
#include <cuda_runtime.h>
#include <cstdint>

// Problem constants
#define MAX_DIST 35.0f
#define BOX 71            // ceil(2*35/1 + 1)
#define FDIM 32
#define BATCH 8
#define NPTS 16384

// Derived sizes (in float4 units)
#define SLICE0_F4 (BOX * BOX * BOX * FDIM / 4)          // 2,863,288
#define TOTAL_F4  (BATCH * BOX * BOX * BOX * FDIM / 4)  // 22,906,304
#define SCATTER_WORK (BATCH * NPTS * (FDIM / 4))        // 1,048,576 point-quads

// Role-split geometry for kernel B: exactly one resident wave on 148 SMs
// (8 CTAs/SM x 256 threads = 2048 threads/SM).
#define NB_SCATTER 128
#define NB_ZERO    1056
#define NB_TOTAL   (NB_SCATTER + NB_ZERO)               // 1184 = 148*8
#define SCATTER_THREADS (NB_SCATTER * 256)              // 32768
#define ZERO_THREADS    (NB_ZERO * 256)                 // 270336

// ---------------------------------------------------------------------------
// Kernel A: zero ONLY batch slice 0 (45.8 MB) — the region the scatter
// atomics depend on. Pure streaming stores, ~1 wave.
// ---------------------------------------------------------------------------
__global__ void zero_slice0_kernel(float4* __restrict__ out) {
    int i = blockIdx.x * blockDim.x + threadIdx.x;
    int stride = gridDim.x * blockDim.x;
    const float4 z = make_float4(0.f, 0.f, 0.f, 0.f);
    for (; i < SLICE0_F4; i += stride) {
        __stcs(&out[i], z);
    }
}

// ---------------------------------------------------------------------------
// Kernel B: role-split, single wave.
//   blocks [0, NB_SCATTER): loop over all scatter work (deep MLP, latency
//     hidden). All B*N points land in batch slice 0 (reference's tf.zeros
//     batch column). Round-half-to-even via __float2int_rn (jnp.round).
//     Out-of-box points add exactly +0.0 in the reference -> skipped.
//     red.global.add.v4.f32 = fire-and-forget vector reduction (REDG).
//   blocks [NB_SCATTER, NB_TOTAL): stream-zero slices 1..7 (320 MB).
// Scatter and memset blocks are co-resident -> true overlap; memset is
// DRAM-bound so losing ~11% of SMs to scatter costs nothing.
// ---------------------------------------------------------------------------
__global__ void __launch_bounds__(256)
role_scatter_zero_kernel(const float* __restrict__ coords,
                         const float4* __restrict__ features4,
                         float* __restrict__ out) {
    if (blockIdx.x < NB_SCATTER) {
        // ---- Scatter role ----
        int t = blockIdx.x * 256 + threadIdx.x;     // 0 .. 32767
        #pragma unroll 4
        for (int w = t; w < SCATTER_WORK; w += SCATTER_THREADS) {
            int p = w >> 3;        // global point index (b*N + n)
            int q = w & 7;         // which float4 of the 8 covering F=32

            float c0 = __ldg(&coords[p * 3 + 0]);
            float c1 = __ldg(&coords[p * 3 + 1]);
            float c2 = __ldg(&coords[p * 3 + 2]);

            int g0 = __float2int_rn(c0 + MAX_DIST);
            int g1 = __float2int_rn(c1 + MAX_DIST);
            int g2 = __float2int_rn(c2 + MAX_DIST);

            if ((unsigned)g0 < BOX && (unsigned)g1 < BOX && (unsigned)g2 < BOX) {
                float4 v = __ldg(&features4[(long long)p * 8 + q]);
                int cell = (g0 * BOX + g1) * BOX + g2;
                float* dst = out + (long long)cell * FDIM + q * 4;  // slice 0
                asm volatile("red.global.add.v4.f32 [%0], {%1, %2, %3, %4};"
                             :: "l"(dst), "f"(v.x), "f"(v.y), "f"(v.z), "f"(v.w)
                             : "memory");
            }
        }
    } else {
        // ---- Zero role: slices 1..7 ----
        float4* out4 = (float4*)out;
        const float4 z = make_float4(0.f, 0.f, 0.f, 0.f);
        long long i = (long long)(blockIdx.x - NB_SCATTER) * 256 + threadIdx.x
                      + SLICE0_F4;
        for (; i < TOTAL_F4; i += ZERO_THREADS) {
            __stcs(&out4[i], z);
        }
    }
}

extern "C" void kernel_launch(void* const* d_in, const int* in_sizes, int n_in,
                              void* d_out, int out_size) {
    const float* coords = (const float*)d_in[0];     // [8,16384,3] f32
    const float4* feats = (const float4*)d_in[1];    // [8,16384,32] f32 as float4
    float* out = (float*)d_out;                      // [8,71,71,71,32] f32

    // Kernel A: zero slice 0 (ordering dependency for the atomics)
    zero_slice0_kernel<<<148 * 8, 256>>>((float4*)out);

    // Kernel B: one-wave role-split scatter + zero of slices 1..7
    role_scatter_zero_kernel<<<NB_TOTAL, 256>>>(coords, feats, out);
}

// round 4
// speedup vs baseline: 1.1375x; 1.1375x over previous
#include <cuda_runtime.h>
#include <cstdint>

// Problem constants
#define MAX_DIST 35.0f
#define BOX 71            // ceil(2*35/1 + 1)
#define FDIM 32
#define BATCH 8
#define NPTS 16384

// Derived sizes (in float4 units)
#define SLICE0_F4 (BOX * BOX * BOX * FDIM / 4)          // 2,863,288
#define TOTAL_F4  (BATCH * BOX * BOX * BOX * FDIM / 4)  // 22,906,304
#define SCATTER_WORK (BATCH * NPTS * (FDIM / 4))        // 1,048,576 point-quads
#define NTHREADS SCATTER_WORK                           // 1 scatter item / thread

// ---------------------------------------------------------------------------
// Fused kernel: 1,048,576 threads (4096 blocks x 256).
//   Each thread:
//     1. issues its scatter input loads (coords + feature quad) up front,
//     2. streams zeros into slices 1..7 (independent stores hide load latency),
//     3. fires one red.global.add.v4.f32 into batch slice 0 mid-stream,
//     4. finishes its zero stripe.
// Scatter semantics (faithful to the reference):
//   - ALL B*N points land in batch slice 0 (reference's tf.zeros batch column)
//   - round-half-to-even via __float2int_rn (jnp.round)
//   - out-of-box points contribute exactly +0.0 -> skipped
// Slice 0 is pre-zeroed by cudaMemsetAsync before this kernel (same stream).
// ---------------------------------------------------------------------------
__global__ void __launch_bounds__(256)
fused_scatter_zero_kernel(const float* __restrict__ coords,
                          const float4* __restrict__ features4,
                          float* __restrict__ out) {
    const int tid = blockIdx.x * blockDim.x + threadIdx.x;

    const int p = tid >> 3;        // global point index (b*N + n)
    const int q = tid & 7;         // which float4 of the 8 covering F=32

    // Issue all scatter inputs NOW; consumed later so the latency hides
    // under the streaming stores below.
    float c0 = __ldg(&coords[p * 3 + 0]);
    float c1 = __ldg(&coords[p * 3 + 1]);
    float c2 = __ldg(&coords[p * 3 + 2]);
    float4 v = __ldg(&features4[(long long)p * 8 + q]);

    float4* out4 = (float4*)out;
    const float4 z = make_float4(0.f, 0.f, 0.f, 0.f);

    // Zero stripe for this thread: i = SLICE0_F4 + tid + k*NTHREADS,
    // k = 0 .. 19 (last few threads stop at TOTAL_F4). ~19.1 iters avg.
    long long i = (long long)SLICE0_F4 + tid;

    // First chunk of zero stores (covers the load latency of the scatter
    // inputs: ~600 cycles DRAM vs 6 independent 16B stores in flight).
    #pragma unroll
    for (int k = 0; k < 6; k++) {
        if (i < TOTAL_F4) { __stcs(&out4[i], z); }
        i += NTHREADS;
    }

    // Scatter: loads have landed by now; fire-and-forget vector reduction.
    {
        int g0 = __float2int_rn(c0 + MAX_DIST);
        int g1 = __float2int_rn(c1 + MAX_DIST);
        int g2 = __float2int_rn(c2 + MAX_DIST);
        if ((unsigned)g0 < BOX && (unsigned)g1 < BOX && (unsigned)g2 < BOX) {
            int cell = (g0 * BOX + g1) * BOX + g2;
            float* dst = out + (long long)cell * FDIM + q * 4;  // slice 0
            asm volatile("red.global.add.v4.f32 [%0], {%1, %2, %3, %4};"
                         :: "l"(dst), "f"(v.x), "f"(v.y), "f"(v.z), "f"(v.w)
                         : "memory");
        }
    }

    // Remaining zero stores.
    for (; i < TOTAL_F4; i += NTHREADS) {
        __stcs(&out4[i], z);
    }
}

extern "C" void kernel_launch(void* const* d_in, const int* in_sizes, int n_in,
                              void* d_out, int out_size) {
    const float* coords = (const float*)d_in[0];     // [8,16384,3] f32
    const float4* feats = (const float4*)d_in[1];    // [8,16384,32] f32 as float4
    float* out = (float*)d_out;                      // [8,71,71,71,32] f32

    // Zero batch slice 0 (the atomics' target) via driver memset —
    // graph-capturable, allocation-free, typically peak-BW.
    size_t slice0_bytes = (size_t)SLICE0_F4 * sizeof(float4);   // 45.8 MB
    cudaMemsetAsync(out, 0, slice0_bytes);

    // Fused scatter + zero of slices 1..7.
    fused_scatter_zero_kernel<<<SCATTER_WORK / 256, 256>>>(coords, feats, out);
}